// round 15
// baseline (speedup 1.0000x reference)
#include <cuda_runtime.h>
#include <cuda_bf16.h>
#include <cstdint>

// out[b] = V @ rho[b] @ V^T,  V = kron(uc[:,2:4], W),  W = kron(ux, uy) (64x64)
// One 128x128 smem tile transformed in place. A passes fused with the global
// load (R9). B passes + epilogue are COLUMN-CHUNKED (4 chunks of 32 paired
// columns): per chunk B-y -> bar -> B-x -> bar -> epilogue, no trailing bar,
// so each chunk's 16.7MB of output stores overlaps the next chunk's FFMAs.

#define RS 132   // row stride (floats), float4-aligned

__device__ __forceinline__ void cache64(float* __restrict__ c,
                                        const float* __restrict__ s)
{
    #pragma unroll
    for (int k = 0; k < 16; k++) {
        float4 v = *(const float4*)(s + k * 4);   // broadcast LDS.128
        c[k * 4 + 0] = v.x; c[k * 4 + 1] = v.y;
        c[k * 4 + 2] = v.z; c[k * 4 + 3] = v.w;
    }
}

extern "C" __global__ void __launch_bounds__(256, 2)
qconv_kernel(const float* __restrict__ rho,
             const float* __restrict__ ux,
             const float* __restrict__ uy,
             const float* __restrict__ uc,
             float* __restrict__ out)
{
    extern __shared__ float s_m[];          // 128 * RS floats (67.5 KB)
    __shared__ float s_ux[64], s_uy[64], s_uc[16];

    const int b = blockIdx.x;
    const int t = threadIdx.x;

    if (t < 64)      { s_ux[t] = ux[t]; s_uy[t] = uy[t]; }
    else if (t < 80) { s_uc[t - 64] = uc[t - 64]; }

    // ---- A-y fused with global load: thread owns (row, half) = 64 contiguous
    //      floats in registers; contract ky with uy (coeffs via __ldg); write once.
    {
        const int row  = t >> 1;
        const int half = t & 1;
        const float4* gp = (const float4*)(rho + (size_t)b * 16384 + row * 128 + half * 64);

        float v[64];
        #pragma unroll
        for (int j = 0; j < 16; j++) {
            float4 x = __ldg(gp + j);
            v[4*j+0] = x.x; v[4*j+1] = x.y; v[4*j+2] = x.z; v[4*j+3] = x.w;
        }

        float* op = s_m + row * RS + half * 64;
        #pragma unroll
        for (int h = 0; h < 2; h++) {       // coefficient half-sweep (iy = h*4..h*4+3)
            float cy[32];
            #pragma unroll
            for (int j = 0; j < 8; j++) {
                float4 x = __ldg((const float4*)uy + h * 8 + j);
                cy[4*j+0] = x.x; cy[4*j+1] = x.y; cy[4*j+2] = x.z; cy[4*j+3] = x.w;
            }
            #pragma unroll
            for (int gl = 0; gl < 8; gl++) {
                float o[4];
                #pragma unroll
                for (int iy = 0; iy < 4; iy++) {
                    float acc = cy[iy * 8] * v[gl * 8];
                    #pragma unroll
                    for (int k = 1; k < 8; k++)
                        acc = fmaf(cy[iy * 8 + k], v[gl * 8 + k], acc);
                    o[iy] = acc;
                }
                *(float4*)(op + gl * 8 + h * 4) = make_float4(o[0], o[1], o[2], o[3]);
            }
        }
    }
    __syncthreads();

    // ---- A-x: contract kx with ux along columns (float4 units, LDS.128 stride 8).
    {
        float cx[64]; cache64(cx, s_ux);
        #pragma unroll
        for (int i = 0; i < 2; i++) {
            int u    = t + i * 256;          // 0..511
            int row  = u & 127;
            int cb   = (u >> 7) & 1;
            int kyq  = u >> 8;
            float* p = s_m + row * RS + cb * 64 + kyq * 4;

            float4 v[8];
            #pragma unroll
            for (int k = 0; k < 8; k++) v[k] = *(float4*)(p + k * 8);
            #pragma unroll
            for (int ix = 0; ix < 8; ix++) {
                float4 o;
                o.x = cx[ix*8] * v[0].x; o.y = cx[ix*8] * v[0].y;
                o.z = cx[ix*8] * v[0].z; o.w = cx[ix*8] * v[0].w;
                #pragma unroll
                for (int k = 1; k < 8; k++) {
                    o.x = fmaf(cx[ix*8+k], v[k].x, o.x);
                    o.y = fmaf(cx[ix*8+k], v[k].y, o.y);
                    o.z = fmaf(cx[ix*8+k], v[k].z, o.z);
                    o.w = fmaf(cx[ix*8+k], v[k].w, o.w);
                }
                *(float4*)(p + ix * 8) = o;
            }
        }
    }
    __syncthreads();

    // ---- Chunked B + epilogue: chunk c owns cols {c*16..c*16+15} u {64+c*16..}.
    //      Per chunk: B-y -> bar -> B-x -> bar -> epilogue (stores), no trailing
    //      bar: stores drain while the next chunk's B-y FFMAs issue.
    const float ga[4] = { s_uc[2], s_uc[6], s_uc[10], s_uc[14] };
    const float gb[4] = { s_uc[3], s_uc[7], s_uc[11], s_uc[15] };
    float* ob = out + (size_t)b * 65536;

    #pragma unroll 1
    for (int c = 0; c < 4; c++) {
        // B-y: contract ky with uy along rows. Unit = (colpair, rg): float2 stride RS.
        {
            float cy[64]; cache64(cy, s_uy);
            int cp  = t & 15;
            int rg  = t >> 4;                // 0..15
            int h   = cp >> 3;
            int cpl = cp & 7;
            float* p = s_m + rg * 8 * RS + h * 64 + c * 16 + cpl * 2;

            float2 v[8];
            #pragma unroll
            for (int k = 0; k < 8; k++) v[k] = *(float2*)(p + k * RS);
            #pragma unroll
            for (int iy = 0; iy < 8; iy++) {
                float ax = cy[iy*8] * v[0].x;
                float ay = cy[iy*8] * v[0].y;
                #pragma unroll
                for (int k = 1; k < 8; k++) {
                    ax = fmaf(cy[iy*8+k], v[k].x, ax);
                    ay = fmaf(cy[iy*8+k], v[k].y, ay);
                }
                *(float2*)(p + iy * RS) = make_float2(ax, ay);
            }
        }
        __syncthreads();

        // B-x: contract kx with ux along rows. Unit = (colpair, cbr, ky): float2 stride 8*RS.
        {
            float cx[64]; cache64(cx, s_ux);
            int cp   = t & 15;
            int rest = t >> 4;               // 0..15
            int ky   = rest & 7;
            int cbr  = rest >> 3;
            int h    = cp >> 3;
            int cpl  = cp & 7;
            float* p = s_m + (cbr * 64 + ky) * RS + h * 64 + c * 16 + cpl * 2;

            float2 v[8];
            #pragma unroll
            for (int k = 0; k < 8; k++) v[k] = *(float2*)(p + k * 8 * RS);
            #pragma unroll
            for (int ix = 0; ix < 8; ix++) {
                float ax = cx[ix*8] * v[0].x;
                float ay = cx[ix*8] * v[0].y;
                #pragma unroll
                for (int k = 1; k < 8; k++) {
                    ax = fmaf(cx[ix*8+k], v[k].x, ax);
                    ay = fmaf(cx[ix*8+k], v[k].y, ay);
                }
                *(float2*)(p + ix * 8 * RS) = make_float2(ax, ay);
            }
        }
        __syncthreads();

        // Epilogue for this chunk: uc-expand, coalesced float4 stores.
        // Unit = (i, jq): jq fastest across lanes for contiguous 64B store runs.
        {
            int jq = t & 3;
            int i  = t >> 2;                 // 0..63
            int j  = c * 16 + jq * 4;

            const float* p00 = s_m + i * RS + j;
            float4 m00 = *(const float4*)p00;
            float4 m01 = *(const float4*)(p00 + 64);
            float4 m10 = *(const float4*)(p00 + 64 * RS);
            float4 m11 = *(const float4*)(p00 + 64 * RS + 64);

            #pragma unroll
            for (int f = 0; f < 4; f++) {
                const float af = ga[f], bf = gb[f];
                float r0[4], r1[4];
                r0[0] = fmaf(af, m00.x, bf * m10.x);
                r0[1] = fmaf(af, m00.y, bf * m10.y);
                r0[2] = fmaf(af, m00.z, bf * m10.z);
                r0[3] = fmaf(af, m00.w, bf * m10.w);
                r1[0] = fmaf(af, m01.x, bf * m11.x);
                r1[1] = fmaf(af, m01.y, bf * m11.y);
                r1[2] = fmaf(af, m01.z, bf * m11.z);
                r1[3] = fmaf(af, m01.w, bf * m11.w);
                float* orow = ob + (size_t)(f * 64 + i) * 256 + j;
                #pragma unroll
                for (int g = 0; g < 4; g++) {
                    const float ag = ga[g], bg = gb[g];
                    float4 v;
                    v.x = fmaf(ag, r0[0], bg * r1[0]);
                    v.y = fmaf(ag, r0[1], bg * r1[1]);
                    v.z = fmaf(ag, r0[2], bg * r1[2]);
                    v.w = fmaf(ag, r0[3], bg * r1[3]);
                    *(float4*)(orow + g * 64) = v;
                }
            }
        }
        // no barrier: next chunk's B-y touches disjoint columns; the bar
        // inside the next iteration protects its B-x.
    }
}

extern "C" void kernel_launch(void* const* d_in, const int* in_sizes, int n_in,
                              void* d_out, int out_size)
{
    const float* rho = (const float*)d_in[0];
    const float* ux  = (const float*)d_in[1];
    const float* uy  = (const float*)d_in[2];
    const float* uc  = (const float*)d_in[3];
    float* out = (float*)d_out;

    const int smem_bytes = 128 * RS * (int)sizeof(float);  // 67584
    cudaFuncSetAttribute(qconv_kernel,
                         cudaFuncAttributeMaxDynamicSharedMemorySize, smem_bytes);

    qconv_kernel<<<256, 256, smem_bytes>>>(rho, ux, uy, uc, out);
}

// round 17
// speedup vs baseline: 1.6372x; 1.6372x over previous
#include <cuda_runtime.h>
#include <cuda_bf16.h>
#include <cstdint>

// out[b] = V @ rho[b] @ V^T,  V = kron(uc[:,2:4], W),  W = kron(ux, uy) (64x64)
// One 128x128 smem tile transformed in place.
//   A-y fused with global load (registers), A-x in smem  [R9-proven]
//   B-y/B-x + epilogue split into 2 column chunks {c*32..+31} u {64+c*32..+31}:
//     B-y -> bar -> B-x -> bar -> epilogue, NO trailing bar, so chunk 0's
//     output stores (33MB chip-wide) drain behind chunk 1's FFMAs.
// All chunked units are float4: LDS.128 runs in 8-lane phases, and each
// 8-lane group hits 32 distinct banks (RS=132 => row shift 4 banks).

#define RS 132   // row stride (floats), float4-aligned

__device__ __forceinline__ void cache64(float* __restrict__ c,
                                        const float* __restrict__ s)
{
    #pragma unroll
    for (int k = 0; k < 16; k++) {
        float4 v = *(const float4*)(s + k * 4);   // broadcast LDS.128
        c[k * 4 + 0] = v.x; c[k * 4 + 1] = v.y;
        c[k * 4 + 2] = v.z; c[k * 4 + 3] = v.w;
    }
}

extern "C" __global__ void __launch_bounds__(256, 2)
qconv_kernel(const float* __restrict__ rho,
             const float* __restrict__ ux,
             const float* __restrict__ uy,
             const float* __restrict__ uc,
             float* __restrict__ out)
{
    extern __shared__ float s_m[];          // 128 * RS floats (67.5 KB)
    __shared__ float s_ux[64], s_uy[64], s_uc[16];

    const int b = blockIdx.x;
    const int t = threadIdx.x;

    if (t < 64)      { s_ux[t] = ux[t]; s_uy[t] = uy[t]; }
    else if (t < 80) { s_uc[t - 64] = uc[t - 64]; }

    // ---- A-y fused with global load: thread owns (row, half) = 64 contiguous
    //      floats in registers; contract ky with uy (coeffs via __ldg); write once.
    {
        const int row  = t >> 1;
        const int half = t & 1;
        const float4* gp = (const float4*)(rho + (size_t)b * 16384 + row * 128 + half * 64);

        float v[64];
        #pragma unroll
        for (int j = 0; j < 16; j++) {
            float4 x = __ldg(gp + j);
            v[4*j+0] = x.x; v[4*j+1] = x.y; v[4*j+2] = x.z; v[4*j+3] = x.w;
        }

        float* op = s_m + row * RS + half * 64;
        #pragma unroll
        for (int h = 0; h < 2; h++) {       // coefficient half-sweep (iy = h*4..h*4+3)
            float cy[32];
            #pragma unroll
            for (int j = 0; j < 8; j++) {
                float4 x = __ldg((const float4*)uy + h * 8 + j);
                cy[4*j+0] = x.x; cy[4*j+1] = x.y; cy[4*j+2] = x.z; cy[4*j+3] = x.w;
            }
            #pragma unroll
            for (int gl = 0; gl < 8; gl++) {
                float o[4];
                #pragma unroll
                for (int iy = 0; iy < 4; iy++) {
                    float acc = cy[iy * 8] * v[gl * 8];
                    #pragma unroll
                    for (int k = 1; k < 8; k++)
                        acc = fmaf(cy[iy * 8 + k], v[gl * 8 + k], acc);
                    o[iy] = acc;
                }
                *(float4*)(op + gl * 8 + h * 4) = make_float4(o[0], o[1], o[2], o[3]);
            }
        }
    }
    __syncthreads();

    // ---- A-x: contract kx with ux along columns (float4 units, LDS.128 stride 8).
    {
        float cx[64]; cache64(cx, s_ux);
        #pragma unroll
        for (int i = 0; i < 2; i++) {
            int u    = t + i * 256;          // 0..511
            int row  = u & 127;
            int cb   = (u >> 7) & 1;
            int kyq  = u >> 8;
            float* p = s_m + row * RS + cb * 64 + kyq * 4;

            float4 v[8];
            #pragma unroll
            for (int k = 0; k < 8; k++) v[k] = *(float4*)(p + k * 8);
            #pragma unroll
            for (int ix = 0; ix < 8; ix++) {
                float4 o;
                o.x = cx[ix*8] * v[0].x; o.y = cx[ix*8] * v[0].y;
                o.z = cx[ix*8] * v[0].z; o.w = cx[ix*8] * v[0].w;
                #pragma unroll
                for (int k = 1; k < 8; k++) {
                    o.x = fmaf(cx[ix*8+k], v[k].x, o.x);
                    o.y = fmaf(cx[ix*8+k], v[k].y, o.y);
                    o.z = fmaf(cx[ix*8+k], v[k].z, o.z);
                    o.w = fmaf(cx[ix*8+k], v[k].w, o.w);
                }
                *(float4*)(p + ix * 8) = o;
            }
        }
    }
    __syncthreads();

    // ---- Chunked B + epilogue. Chunk c owns cols {c*32..+31} u {64+c*32..+31}.
    float* ob = out + (size_t)b * 65536;

    #pragma unroll
    for (int c = 0; c < 2; c++) {
        const int colq = (t & 7) * 4 + ((t >> 3) & 1) * 64 + c * 32; // lane->column base
        // (For B passes: q = t&15 -> col; 8-lane phases each span banks {0,4,..,28}+const)

        // B-y: contract ky with uy along rows. Unit = (q, rg): float4, stride RS.
        {
            float cy[64]; cache64(cy, s_uy);
            int q   = t & 15;
            int rg  = t >> 4;                // 0..15
            int col = (q & 7) * 4 + (q >> 3) * 64 + c * 32;
            float* p = s_m + rg * 8 * RS + col;

            float4 v[8];
            #pragma unroll
            for (int k = 0; k < 8; k++) v[k] = *(float4*)(p + k * RS);
            #pragma unroll
            for (int iy = 0; iy < 8; iy++) {
                float4 o;
                o.x = cy[iy*8] * v[0].x; o.y = cy[iy*8] * v[0].y;
                o.z = cy[iy*8] * v[0].z; o.w = cy[iy*8] * v[0].w;
                #pragma unroll
                for (int k = 1; k < 8; k++) {
                    o.x = fmaf(cy[iy*8+k], v[k].x, o.x);
                    o.y = fmaf(cy[iy*8+k], v[k].y, o.y);
                    o.z = fmaf(cy[iy*8+k], v[k].z, o.z);
                    o.w = fmaf(cy[iy*8+k], v[k].w, o.w);
                }
                *(float4*)(p + iy * RS) = o;
            }
        }
        __syncthreads();

        // B-x: contract kx with ux along rows. Unit = (q, cbr, ky): float4, stride 8*RS.
        {
            float cx[64]; cache64(cx, s_ux);
            int q    = t & 15;
            int rest = t >> 4;               // 0..15
            int ky   = rest & 7;
            int cbr  = rest >> 3;
            int col  = (q & 7) * 4 + (q >> 3) * 64 + c * 32;
            float* p = s_m + (cbr * 64 + ky) * RS + col;

            float4 v[8];
            #pragma unroll
            for (int k = 0; k < 8; k++) v[k] = *(float4*)(p + k * 8 * RS);
            #pragma unroll
            for (int ix = 0; ix < 8; ix++) {
                float4 o;
                o.x = cx[ix*8] * v[0].x; o.y = cx[ix*8] * v[0].y;
                o.z = cx[ix*8] * v[0].z; o.w = cx[ix*8] * v[0].w;
                #pragma unroll
                for (int k = 1; k < 8; k++) {
                    o.x = fmaf(cx[ix*8+k], v[k].x, o.x);
                    o.y = fmaf(cx[ix*8+k], v[k].y, o.y);
                    o.z = fmaf(cx[ix*8+k], v[k].z, o.z);
                    o.w = fmaf(cx[ix*8+k], v[k].w, o.w);
                }
                *(float4*)(p + ix * 8 * RS) = o;
            }
        }
        __syncthreads();

        // Epilogue chunk c: uc-expand cols {c*32..+31} (paired with +64), store.
        {
            const float ga[4] = { s_uc[2], s_uc[6], s_uc[10], s_uc[14] };
            const float gb[4] = { s_uc[3], s_uc[7], s_uc[11], s_uc[15] };
            #pragma unroll
            for (int it = 0; it < 2; it++) {
                int u  = t + it * 256;       // 0..511
                int jq = u & 7;              // 0..7
                int i  = u >> 3;             // 0..63
                int j  = c * 32 + jq * 4;

                const float* p00 = s_m + i * RS + j;
                float4 m00 = *(const float4*)p00;
                float4 m01 = *(const float4*)(p00 + 64);
                float4 m10 = *(const float4*)(p00 + 64 * RS);
                float4 m11 = *(const float4*)(p00 + 64 * RS + 64);

                #pragma unroll
                for (int f = 0; f < 4; f++) {
                    const float af = ga[f], bf = gb[f];
                    float r0[4], r1[4];
                    r0[0] = fmaf(af, m00.x, bf * m10.x);
                    r0[1] = fmaf(af, m00.y, bf * m10.y);
                    r0[2] = fmaf(af, m00.z, bf * m10.z);
                    r0[3] = fmaf(af, m00.w, bf * m10.w);
                    r1[0] = fmaf(af, m01.x, bf * m11.x);
                    r1[1] = fmaf(af, m01.y, bf * m11.y);
                    r1[2] = fmaf(af, m01.z, bf * m11.z);
                    r1[3] = fmaf(af, m01.w, bf * m11.w);
                    float* orow = ob + (size_t)(f * 64 + i) * 256 + j;
                    #pragma unroll
                    for (int g = 0; g < 4; g++) {
                        const float ag = ga[g], bg = gb[g];
                        float4 v;
                        v.x = fmaf(ag, r0[0], bg * r1[0]);
                        v.y = fmaf(ag, r0[1], bg * r1[1]);
                        v.z = fmaf(ag, r0[2], bg * r1[2]);
                        v.w = fmaf(ag, r0[3], bg * r1[3]);
                        *(float4*)(orow + g * 64) = v;
                    }
                }
            }
        }
        // no trailing barrier: chunk c+1's B-y touches disjoint columns,
        // so these stores drain behind its FFMAs.
    }
}

extern "C" void kernel_launch(void* const* d_in, const int* in_sizes, int n_in,
                              void* d_out, int out_size)
{
    const float* rho = (const float*)d_in[0];
    const float* ux  = (const float*)d_in[1];
    const float* uy  = (const float*)d_in[2];
    const float* uc  = (const float*)d_in[3];
    float* out = (float*)d_out;

    const int smem_bytes = 128 * RS * (int)sizeof(float);  // 67584
    cudaFuncSetAttribute(qconv_kernel,
                         cudaFuncAttributeMaxDynamicSharedMemorySize, smem_bytes);

    qconv_kernel<<<256, 256, smem_bytes>>>(rho, ux, uy, uc, out);
}